// round 4
// baseline (speedup 1.0000x reference)
#include <cuda_runtime.h>

#define N_PTS   20000
#define BB      2
#define PP      2048
#define C_FEAT  64
#define SS      32
#define NQ      (BB*PP)                 // 4096 query points
#define OUT_F   (BB*(C_FEAT+3)*PP*SS)   // 8781824 floats for new_features
#define G       12                      // grid dim: 1/12 = 0.0833 >= R = 0.08
#define NCELLS  (G*G*G)                 // 1728
#define MAXBUF  128                     // in-ball cap per query (lambda ~ 43)
#define QWARPS  4                       // warps per block in query kernel

// Scratch (allocation-free rule: __device__ globals)
__device__ float4 g_pts[N_PTS];               // x, y, z, |p|^2 (original order)
__device__ int    g_pt_cell[N_PTS];
__device__ int    g_cell_start[NCELLS + 1];
__device__ float4 g_sorted_pts[N_PTS];        // cell-sorted
__device__ int    g_sorted_idx[N_PTS];        // original index per sorted slot
__device__ float  g_featT[N_PTS * C_FEAT];    // transposed features [n][c]

// ---------------------------------------------------------------------------
// K_A: ONE launch for all preprocessing.
//   block 0          : grid build (smem hist -> smem scan -> scatter)
//   blocks 1..1250   : feature transpose (C,N) -> (N,C)
// ---------------------------------------------------------------------------
__global__ void __launch_bounds__(1024)
fused_prep_kernel(const float* __restrict__ xyz, const float* __restrict__ f) {
    __shared__ int   hist[NCELLS];     // histogram, then reused as scatter cursor
    __shared__ int   scanbuf[1024];
    __shared__ float tile[32][33];

    const int t = threadIdx.x;

    if (blockIdx.x == 0) {
        // ---- phase 1: points, cells, histogram ----
        for (int i = t; i < NCELLS; i += 1024) hist[i] = 0;
        __syncthreads();
        for (int i = t; i < N_PTS; i += 1024) {
            float x = xyz[3 * i + 0];
            float y = xyz[3 * i + 1];
            float z = xyz[3 * i + 2];
            float n2 = fmaf(z, z, fmaf(y, y, x * x));
            g_pts[i] = make_float4(x, y, z, n2);
            int cx = min(G - 1, max(0, (int)(x * G)));
            int cy = min(G - 1, max(0, (int)(y * G)));
            int cz = min(G - 1, max(0, (int)(z * G)));
            int cell = (cz * G + cy) * G + cx;
            g_pt_cell[i] = cell;
            atomicAdd(&hist[cell], 1);
        }
        __syncthreads();

        // ---- phase 2: exclusive scan (2 cells per thread + block scan) ----
        int i0 = 2 * t, i1 = 2 * t + 1;
        int v0 = (i0 < NCELLS) ? hist[i0] : 0;
        int v1 = (i1 < NCELLS) ? hist[i1] : 0;
        scanbuf[t] = v0 + v1;
        __syncthreads();
        for (int off = 1; off < 1024; off <<= 1) {
            int vv = (t >= off) ? scanbuf[t - off] : 0;
            __syncthreads();
            scanbuf[t] += vv;
            __syncthreads();
        }
        int toff = (t > 0) ? scanbuf[t - 1] : 0;   // exclusive offset for pair
        __syncthreads();                            // before hist reuse as cursor
        if (i0 < NCELLS) {
            g_cell_start[i0] = toff;
            hist[i0] = toff;                        // cursor
            g_cell_start[i1] = toff + v0;
            hist[i1] = toff + v0;
        } else if (i0 == NCELLS) {
            g_cell_start[NCELLS] = toff;            // total = N_PTS
        }
        __syncthreads();

        // ---- phase 3: scatter into cell-sorted order ----
        for (int i = t; i < N_PTS; i += 1024) {
            int cell = g_pt_cell[i];
            float4 p = g_pts[i];
            int pos = atomicAdd(&hist[cell], 1);
            g_sorted_pts[pos] = p;
            g_sorted_idx[pos] = i;
        }
    } else {
        // ---- feature transpose, 32x32 tile, 1024 threads = 1 elem each ----
        int bt = blockIdx.x - 1;          // 0..1249
        int n0 = (bt % 625) * 32;
        int c0 = (bt / 625) * 32;
        int tx = t & 31;
        int ty = t >> 5;                  // 0..31
        tile[ty][tx] = f[(size_t)(c0 + ty) * N_PTS + n0 + tx];
        __syncthreads();
        g_featT[(size_t)(n0 + ty) * C_FEAT + c0 + tx] = tile[tx][ty];
    }
}

// ---------------------------------------------------------------------------
// Warp-collective bitonic sort of 128 int keys (4 regs/lane, e = j*32+lane).
// Ascending; smallest 32 land in k[0] across lanes 0..31.
// ---------------------------------------------------------------------------
__device__ __forceinline__ void bitonic128(int k[4], int lane) {
#pragma unroll
    for (int size = 2; size <= 128; size <<= 1) {
#pragma unroll
        for (int stride = size >> 1; stride > 0; stride >>= 1) {
            if (stride >= 32) {
                int sj = stride >> 5;     // 1 or 2
#pragma unroll
                for (int j = 0; j < 4; j++) {
                    if ((j & sj) == 0) {
                        int pj = j | sj;
                        int e = j * 32 + lane;
                        bool up = ((e & size) == 0);
                        int a = k[j], b = k[pj];
                        int lo = min(a, b), hi = max(a, b);
                        k[j]  = up ? lo : hi;
                        k[pj] = up ? hi : lo;
                    }
                }
            } else {
#pragma unroll
                for (int j = 0; j < 4; j++) {
                    int e = j * 32 + lane;
                    bool up = ((e & size) == 0);
                    int other = __shfl_xor_sync(0xffffffffu, k[j], stride);
                    bool keepMin = (((lane & stride) == 0) == up);
                    k[j] = keepMin ? min(k[j], other) : max(k[j], other);
                }
            }
        }
    }
}

// ---------------------------------------------------------------------------
// K_B: grid ball-query + group. One warp per query. Epilogue stages the
// gathered [67][32] tile in smem (cooperative per-point 256B loads -> 2-3
// cache lines instead of 32) and writes fully coalesced channel rows.
// ---------------------------------------------------------------------------
__global__ void __launch_bounds__(QWARPS * 32)
query_group_kernel(const float* __restrict__ new_xyz,
                   float* __restrict__ out,
                   int write_idn) {
    __shared__ int    buf[QWARPS][MAXBUF];
    __shared__ float  sfeat[QWARPS][C_FEAT * 33];   // [c][s], s-padded to 33
    __shared__ float4 sxyz[QWARPS][SS];

    const int tid  = threadIdx.x;
    const int w    = tid >> 5;
    const int lane = tid & 31;
    const int q    = blockIdx.x * QWARPS + w;     // 0..4095
    const int b    = q >> 11;
    const int p    = q & 2047;

    const float qx = new_xyz[3 * q + 0];
    const float qy = new_xyz[3 * q + 1];
    const float qz = new_xyz[3 * q + 2];
    const float q2 = fmaf(qz, qz, fmaf(qy, qy, qx * qx));
    const float R2 = (float)(0.08 * 0.08);
    const unsigned lmask = (1u << lane) - 1u;

    const int cxq = min(G - 1, max(0, (int)(qx * G)));
    const int cyq = min(G - 1, max(0, (int)(qy * G)));
    const int czq = min(G - 1, max(0, (int)(qz * G)));
    const int xlo = max(cxq - 1, 0), xhi = min(cxq + 1, G - 1);
    const int ylo = max(cyq - 1, 0), yhi = min(cyq + 1, G - 1);
    const int zlo = max(czq - 1, 0), zhi = min(czq + 1, G - 1);

    int count = 0;
    // x-adjacent cells contiguous -> one range per (z,y): <= 9 ranges
    for (int cz = zlo; cz <= zhi; cz++) {
        for (int cy = ylo; cy <= yhi; cy++) {
            int rowbase = (cz * G + cy) * G;
            int rs = g_cell_start[rowbase + xlo];
            int re = g_cell_start[rowbase + xhi + 1];
            for (int base = rs; base < re; base += 32) {
                int i = base + lane;
                bool v = i < re;
                float4 pt = v ? g_sorted_pts[i] : make_float4(0.f, 0.f, 0.f, 1e30f);
                // reference arithmetic: (q2 + |p|^2) - 2*cross, same FMA shape
                float cross = fmaf(qz, pt.z, fmaf(qy, pt.y, qx * pt.x));
                float d2 = fmaf(-2.0f, cross, q2 + pt.w);
                bool pred = v && (d2 < R2);
                unsigned m = __ballot_sync(0xffffffffu, pred);
                if (pred) {
                    int slot = count + __popc(m & lmask);
                    if (slot < MAXBUF) buf[w][slot] = g_sorted_idx[i];
                }
                count += __popc(m);
            }
        }
    }
    __syncwarp();

    int nbuf = min(count, MAXBUF);
    int k[4];
#pragma unroll
    for (int j = 0; j < 4; j++) {
        int e = j * 32 + lane;
        k[j] = (e < nbuf) ? buf[w][e] : 0x7fffffff;
    }
    bitonic128(k, lane);
    // ranks 0..31 live in k[0] across lanes

    int first = __shfl_sync(0xffffffffu, k[0], 0);
    int c32   = min(count, SS);
    int sel   = (lane < c32) ? k[0] : ((count > 0) ? first : 0);
    float idnv = (count == 0 || lane < count) ? 1.0f : 0.0f;

    // ---- stage gathered tile in smem (few cache lines per point) ----
    const float4* __restrict__ ft = (const float4*)g_featT;
#pragma unroll 4
    for (int s = 0; s < SS; s++) {
        int sel_s = __shfl_sync(0xffffffffu, sel, s);
        if (lane < 16) {
            float4 v = ft[sel_s * (C_FEAT / 4) + lane];   // 256B contiguous
            int c = 4 * lane;
            sfeat[w][(c + 0) * 33 + s] = v.x;
            sfeat[w][(c + 1) * 33 + s] = v.y;
            sfeat[w][(c + 2) * 33 + s] = v.z;
            sfeat[w][(c + 3) * 33 + s] = v.w;
        } else if (lane == 16) {
            sxyz[w][s] = g_pts[sel_s];
        }
    }
    __syncwarp();

    // ---- coalesced output writes ----
    const size_t cs = (size_t)PP * SS;
    size_t ob = (((size_t)b * (C_FEAT + 3)) * PP + p) * SS + lane;

    float4 psv = sxyz[w][lane];
    out[ob + 0 * cs] = psv.x - qx;
    out[ob + 1 * cs] = psv.y - qy;
    out[ob + 2 * cs] = psv.z - qz;

    size_t o = ob + 3 * cs;
#pragma unroll 8
    for (int c = 0; c < C_FEAT; c++) {
        out[o] = sfeat[w][c * 33 + lane];
        o += cs;
    }

    if (write_idn)
        out[(size_t)OUT_F + (size_t)q * SS + lane] = idnv;
}

// ---------------------------------------------------------------------------
extern "C" void kernel_launch(void* const* d_in, const int* in_sizes, int n_in,
                              void* d_out, int out_size) {
    const float* xyz      = (const float*)d_in[0];   // (20000, 3)
    const float* new_xyz  = (const float*)d_in[1];   // (2, 2048, 3)
    const float* features = (const float*)d_in[2];   // (64, 20000)
    float* out = (float*)d_out;

    fused_prep_kernel<<<1 + 625 * 2, 1024>>>(xyz, features);

    int write_idn = (out_size >= OUT_F + NQ * SS) ? 1 : 0;
    query_group_kernel<<<NQ / QWARPS, QWARPS * 32>>>(new_xyz, out, write_idn);
}

// round 13
// speedup vs baseline: 1.5685x; 1.5685x over previous
#include <cuda_runtime.h>

#define N_PTS   20000
#define BB      2
#define PP      2048
#define C_FEAT  64
#define SS      32
#define NQ      (BB*PP)                 // 4096 query points
#define OUT_F   (BB*(C_FEAT+3)*PP*SS)   // 8781824 floats for new_features
#define G       12                      // grid dim: 1/12 = 0.0833 >= R = 0.08
#define NCELLS  (G*G*G)                 // 1728
#define CAP     64                      // slab capacity per cell (lambda ~11.6)
#define MAXBUF  128                     // in-ball cap per query (lambda ~43, >12 sigma)
#define TCAP    640                     // candidate map cap (~313 expected)
#define QWARPS  8                       // warps per block in query kernel

// Scratch (allocation-free rule: __device__ globals)
__device__ float4 g_pts[N_PTS];               // x,y,z,|p|^2 in ORIGINAL order (epilogue)
__device__ int    g_cell_cnt[NCELLS];         // zeroed via memset node
__device__ float4 g_cell_pts[NCELLS * CAP];   // slab: points by cell (arbitrary order)
__device__ int    g_cell_pidx[NCELLS * CAP];  // slab: original index
__device__ float  g_featT[N_PTS * C_FEAT];    // transposed features [n][c]

// ---------------------------------------------------------------------------
// K1 (fully parallel fusion):
//   blocks 0..78     : point prep + atomic append into cell slabs
//   blocks 79..1328  : feature transpose (C,N) -> (N,C)
// ---------------------------------------------------------------------------
__global__ void __launch_bounds__(256)
fill_transpose_kernel(const float* __restrict__ xyz, const float* __restrict__ f) {
    if (blockIdx.x < 79) {
        int i = blockIdx.x * 256 + threadIdx.x;
        if (i < N_PTS) {
            float x = xyz[3 * i + 0];
            float y = xyz[3 * i + 1];
            float z = xyz[3 * i + 2];
            // EXACT R3 norm chain (rel_err 0.0 proven) — do not reassociate
            float n2 = fmaf(z, z, fmaf(y, y, x * x));
            float4 p = make_float4(x, y, z, n2);
            g_pts[i] = p;
            int cx = min(G - 1, max(0, (int)(x * G)));
            int cy = min(G - 1, max(0, (int)(y * G)));
            int cz = min(G - 1, max(0, (int)(z * G)));
            int cell = (cz * G + cy) * G + cx;
            int pos = atomicAdd(&g_cell_cnt[cell], 1);
            if (pos < CAP) {                      // statistically never overflows
                g_cell_pts[cell * CAP + pos]  = p;
                g_cell_pidx[cell * CAP + pos] = i;
            }
        }
    } else {
        __shared__ float tile[32][33];
        int t  = blockIdx.x - 79;         // 0..1249
        int n0 = (t % 625) * 32;
        int c0 = (t / 625) * 32;
        int tx = threadIdx.x & 31;
        int ty = threadIdx.x >> 5;        // 0..7
#pragma unroll
        for (int j = 0; j < 4; j++)
            tile[ty + j * 8][tx] = f[(size_t)(c0 + ty + j * 8) * N_PTS + n0 + tx];
        __syncthreads();
#pragma unroll
        for (int j = 0; j < 4; j++)
            g_featT[(size_t)(n0 + ty + j * 8) * C_FEAT + c0 + tx] = tile[tx][ty + j * 8];
    }
}

// ---------------------------------------------------------------------------
// Warp-collective bitonic sort of 128 int keys (4 regs/lane, e = j*32+lane).
// Ascending; smallest 32 land in k[0] across lanes 0..31.  (R3-proven)
// ---------------------------------------------------------------------------
__device__ __forceinline__ void bitonic128(int k[4], int lane) {
#pragma unroll
    for (int size = 2; size <= 128; size <<= 1) {
#pragma unroll
        for (int stride = size >> 1; stride > 0; stride >>= 1) {
            if (stride >= 32) {
                int sj = stride >> 5;     // 1 or 2
#pragma unroll
                for (int j = 0; j < 4; j++) {
                    if ((j & sj) == 0) {
                        int pj = j | sj;
                        int e = j * 32 + lane;
                        bool up = ((e & size) == 0);
                        int a = k[j], b = k[pj];
                        int lo = min(a, b), hi = max(a, b);
                        k[j]  = up ? lo : hi;
                        k[pj] = up ? hi : lo;
                    }
                }
            } else {
#pragma unroll
                for (int j = 0; j < 4; j++) {
                    int e = j * 32 + lane;
                    bool up = ((e & size) == 0);
                    int other = __shfl_xor_sync(0xffffffffu, k[j], stride);
                    bool keepMin = (((lane & stride) == 0) == up);
                    k[j] = keepMin ? min(k[j], other) : max(k[j], other);
                }
            }
        }
    }
}

// ---------------------------------------------------------------------------
// K2: grid ball-query + group. One warp per query.
// Packed enumeration: prefix-scan 27 cell counts -> dense smem map of slab
// addresses -> ~10 fully packed 32-lane candidate chunks (indep. -> MLP).
// Epilogue = R3's direct per-lane gather (high MLP, proven fast).
// ---------------------------------------------------------------------------
__global__ void __launch_bounds__(QWARPS * 32)
query_group_kernel(const float* __restrict__ new_xyz,
                   float* __restrict__ out,
                   int write_idn) {
    __shared__ int buf[QWARPS][MAXBUF];
    __shared__ int smap[QWARPS][TCAP];

    const int tid  = threadIdx.x;
    const int w    = tid >> 5;
    const int lane = tid & 31;
    const int q    = blockIdx.x * QWARPS + w;     // 0..4095
    const int b    = q >> 11;
    const int p    = q & 2047;

    const float qx = new_xyz[3 * q + 0];
    const float qy = new_xyz[3 * q + 1];
    const float qz = new_xyz[3 * q + 2];
    const float q2 = fmaf(qz, qz, fmaf(qy, qy, qx * qx));
    const float R2 = (float)(0.08 * 0.08);
    const unsigned lmask = (1u << lane) - 1u;

    const int cxq = min(G - 1, max(0, (int)(qx * G)));
    const int cyq = min(G - 1, max(0, (int)(qy * G)));
    const int czq = min(G - 1, max(0, (int)(qz * G)));

    // lane<27 -> one neighbor cell
    int cnt = 0, cell = 0;
    if (lane < 27) {
        int dx = lane % 3 - 1;
        int dy = (lane / 3) % 3 - 1;
        int dz = lane / 9 - 1;
        int cx = cxq + dx, cy = cyq + dy, cz = czq + dz;
        if (cx >= 0 && cx < G && cy >= 0 && cy < G && cz >= 0 && cz < G) {
            cell = (cz * G + cy) * G + cx;
            cnt  = min(g_cell_cnt[cell], CAP);
        }
    }
    // warp inclusive scan of cnt
    int incl = cnt;
#pragma unroll
    for (int off = 1; off < 32; off <<= 1) {
        int n = __shfl_up_sync(0xffffffffu, incl, off);
        if (lane >= off) incl += n;
    }
    const int excl = incl - cnt;
    const int T = __shfl_sync(0xffffffffu, incl, 31);

    // dense candidate map: smap[c] = slab address
    if (lane < 27) {
        int base = cell * CAP;
        for (int j = 0; j < cnt; j++) {
            int c = excl + j;
            if (c < TCAP) smap[w][c] = base + j;
        }
    }
    __syncwarp();

    // packed candidate chunks
    const float4* __restrict__ cpts = g_cell_pts;
    const int*    __restrict__ cidx = g_cell_pidx;
    int count = 0;
    const int Tc = min(T, TCAP);
    for (int c0 = 0; c0 < Tc; c0 += 32) {
        int c = c0 + lane;
        bool v = c < Tc;
        float4 pt = make_float4(0.f, 0.f, 0.f, 1e30f);
        int pidx = 0;
        if (v) {
            int a = smap[w][c];
            pt   = cpts[a];
            pidx = cidx[a];
        }
        // EXACT R3 distance chain: (q2 + |p|^2) - 2*cross
        float cross = fmaf(qz, pt.z, fmaf(qy, pt.y, qx * pt.x));
        float d2 = fmaf(-2.0f, cross, q2 + pt.w);
        bool pred = v && (d2 < R2);
        unsigned m = __ballot_sync(0xffffffffu, pred);
        if (pred) {
            int slot = count + __popc(m & lmask);
            if (slot < MAXBUF) buf[w][slot] = pidx;
        }
        count += __popc(m);
    }
    __syncwarp();

    // sort candidates by original index; ranks 0..31 -> k[0]
    int nbuf = min(count, MAXBUF);
    int k[4];
#pragma unroll
    for (int j = 0; j < 4; j++) {
        int e = j * 32 + lane;
        k[j] = (e < nbuf) ? buf[w][e] : 0x7fffffff;
    }
    bitonic128(k, lane);

    int first = __shfl_sync(0xffffffffu, k[0], 0);
    int c32   = min(count, SS);
    int sel   = (lane < c32) ? k[0] : ((count > 0) ? first : 0);
    float idnv = (count == 0 || lane < count) ? 1.0f : 0.0f;

    // ---- R3 epilogue: direct gathers, high MLP ----
    float4 ps = g_pts[sel];
    const size_t cs = (size_t)PP * SS;
    size_t ob = (((size_t)b * (C_FEAT + 3)) * PP + p) * SS + lane;
    out[ob + 0 * cs] = ps.x - qx;
    out[ob + 1 * cs] = ps.y - qy;
    out[ob + 2 * cs] = ps.z - qz;

    const float4* __restrict__ ft = (const float4*)g_featT;
    int fb = sel * (C_FEAT / 4);
    size_t o = ob + 3 * cs;
#pragma unroll
    for (int g = 0; g < C_FEAT / 4; g++) {
        float4 vv = ft[fb + g];
        out[o] = vv.x; o += cs;
        out[o] = vv.y; o += cs;
        out[o] = vv.z; o += cs;
        out[o] = vv.w; o += cs;
    }

    if (write_idn)
        out[(size_t)OUT_F + (size_t)q * SS + lane] = idnv;
}

// ---------------------------------------------------------------------------
extern "C" void kernel_launch(void* const* d_in, const int* in_sizes, int n_in,
                              void* d_out, int out_size) {
    const float* xyz      = (const float*)d_in[0];   // (20000, 3)
    const float* new_xyz  = (const float*)d_in[1];   // (2, 2048, 3)
    const float* features = (const float*)d_in[2];   // (64, 20000)
    float* out = (float*)d_out;

    void* cnt_ptr = nullptr;
    cudaGetSymbolAddress(&cnt_ptr, g_cell_cnt);
    cudaMemsetAsync(cnt_ptr, 0, NCELLS * sizeof(int));

    fill_transpose_kernel<<<79 + 1250, 256>>>(xyz, features);

    int write_idn = (out_size >= OUT_F + NQ * SS) ? 1 : 0;
    query_group_kernel<<<NQ / QWARPS, QWARPS * 32>>>(new_xyz, out, write_idn);
}

// round 14
// speedup vs baseline: 2.1585x; 1.3762x over previous
#include <cuda_runtime.h>

#define N_PTS   20000
#define BB      2
#define PP      2048
#define C_FEAT  64
#define SS      32
#define NQ      (BB*PP)                 // 4096 query points
#define OUT_F   (BB*(C_FEAT+3)*PP*SS)   // 8781824 floats for new_features
#define G       12                      // grid dim: 1/12 = 0.0833 >= R = 0.08
#define NCELLS  (G*G*G)                 // 1728
#define MAXBUF  128                     // per-warp candidate cap (~22 expected)
#define QW      8                       // queries per block (x2 warps each)

// Scratch (allocation-free rule: __device__ globals)
__device__ float4 g_pts[N_PTS];               // x,y,z,|p|^2 (original order)
__device__ int    g_pt_cell[N_PTS];
__device__ int    g_cell_count[NCELLS];       // zeroed via memset node
__device__ int    g_cell_start[NCELLS + 1];
__device__ int    g_cell_cursor[NCELLS];
__device__ float4 g_sorted_pts[N_PTS];        // cell-sorted (dense!)
__device__ int    g_sorted_idx[N_PTS];
__device__ float  g_featT[N_PTS * C_FEAT];    // transposed features [n][c]

// ---------------------------------------------------------------------------
// K1: SoA points + squared norm + cell id + cell histogram   (R3-proven)
// ---------------------------------------------------------------------------
__global__ void prep_hist_kernel(const float* __restrict__ xyz) {
    int i = blockIdx.x * 256 + threadIdx.x;
    if (i < N_PTS) {
        float x = xyz[3 * i + 0];
        float y = xyz[3 * i + 1];
        float z = xyz[3 * i + 2];
        float n2 = fmaf(z, z, fmaf(y, y, x * x));
        g_pts[i] = make_float4(x, y, z, n2);
        int cx = min(G - 1, max(0, (int)(x * G)));
        int cy = min(G - 1, max(0, (int)(y * G)));
        int cz = min(G - 1, max(0, (int)(z * G)));
        int cell = (cz * G + cy) * G + cx;
        g_pt_cell[i] = cell;
        atomicAdd(&g_cell_count[cell], 1);
    }
}

// ---------------------------------------------------------------------------
// K2: block 0 = exclusive scan of cell counts; blocks 1.. = transpose (R3)
// ---------------------------------------------------------------------------
__global__ void __launch_bounds__(256)
scan_transpose_kernel(const float* __restrict__ f) {
    if (blockIdx.x == 0) {
        __shared__ int spart[256];
        int t = threadIdx.x;
        int local[7];
        int s = 0;
#pragma unroll
        for (int r = 0; r < 7; r++) {
            int idx = t * 7 + r;
            int v = (idx < NCELLS) ? g_cell_count[idx] : 0;
            local[r] = s;
            s += v;
        }
        spart[t] = s;
        __syncthreads();
        for (int off = 1; off < 256; off <<= 1) {
            int v = (t >= off) ? spart[t - off] : 0;
            __syncthreads();
            spart[t] += v;
            __syncthreads();
        }
        int toff = (t > 0) ? spart[t - 1] : 0;
#pragma unroll
        for (int r = 0; r < 7; r++) {
            int idx = t * 7 + r;
            if (idx <= NCELLS) {
                int st = toff + local[r];
                g_cell_start[idx] = st;
                if (idx < NCELLS) g_cell_cursor[idx] = st;
            }
        }
    } else {
        __shared__ float tile[32][33];
        int t  = blockIdx.x - 1;          // 0..1249
        int n0 = (t % 625) * 32;
        int c0 = (t / 625) * 32;
        int tx = threadIdx.x & 31;
        int ty = threadIdx.x >> 5;        // 0..7
#pragma unroll
        for (int j = 0; j < 4; j++)
            tile[ty + j * 8][tx] = f[(size_t)(c0 + ty + j * 8) * N_PTS + n0 + tx];
        __syncthreads();
#pragma unroll
        for (int j = 0; j < 4; j++)
            g_featT[(size_t)(n0 + ty + j * 8) * C_FEAT + c0 + tx] = tile[tx][ty + j * 8];
    }
}

// ---------------------------------------------------------------------------
// K3: scatter points into dense cell-sorted order   (R3-proven)
// ---------------------------------------------------------------------------
__global__ void scatter_kernel() {
    int i = blockIdx.x * 256 + threadIdx.x;
    if (i < N_PTS) {
        int cell = g_pt_cell[i];
        int pos = atomicAdd(&g_cell_cursor[cell], 1);
        g_sorted_pts[pos] = g_pts[i];
        g_sorted_idx[pos] = i;
    }
}

// ---------------------------------------------------------------------------
// Warp-collective bitonic sort of 128 int keys. Ascending; smallest 32 -> k[0].
// ---------------------------------------------------------------------------
__device__ __forceinline__ void bitonic128(int k[4], int lane) {
#pragma unroll
    for (int size = 2; size <= 128; size <<= 1) {
#pragma unroll
        for (int stride = size >> 1; stride > 0; stride >>= 1) {
            if (stride >= 32) {
                int sj = stride >> 5;
#pragma unroll
                for (int j = 0; j < 4; j++) {
                    if ((j & sj) == 0) {
                        int pj = j | sj;
                        int e = j * 32 + lane;
                        bool up = ((e & size) == 0);
                        int a = k[j], b = k[pj];
                        int lo = min(a, b), hi = max(a, b);
                        k[j]  = up ? lo : hi;
                        k[pj] = up ? hi : lo;
                    }
                }
            } else {
#pragma unroll
                for (int j = 0; j < 4; j++) {
                    int e = j * 32 + lane;
                    bool up = ((e & size) == 0);
                    int other = __shfl_xor_sync(0xffffffffu, k[j], stride);
                    bool keepMin = (((lane & stride) == 0) == up);
                    k[j] = keepMin ? min(k[j], other) : max(k[j], other);
                }
            }
        }
    }
}

// ---------------------------------------------------------------------------
// K4: grid ball-query + group, TWO warps per query (8192 warps -> occ ~60%).
// Warp pair splits the <=9 (z,y) ranges by parity; each ballot-collects +
// bitonic-sorts its own candidates; pair merges smallest-32 via bitonic
// half-cleaner (C[l] = min(A[l], B[31-l]) is the smallest 32, bitonic ->
// 5-stage shfl sort). Epilogue split: warp0 xyz+feat[0:32], warp1 feat[32:64]+idn.
// ---------------------------------------------------------------------------
__global__ void __launch_bounds__(QW * 64)
query_group_kernel(const float* __restrict__ new_xyz,
                   float* __restrict__ out,
                   int write_idn) {
    __shared__ int buf[QW * 2][MAXBUF];
    __shared__ int pair[QW][2][SS];
    __shared__ int pcnt[QW][2];

    const int tid  = threadIdx.x;
    const int wq   = tid >> 5;          // 0..15
    const int lane = tid & 31;
    const int s    = wq >> 1;           // query slot 0..7
    const int sub  = wq & 1;            // half index
    const int q    = blockIdx.x * QW + s;
    const int b    = q >> 11;
    const int p    = q & 2047;

    const float qx = new_xyz[3 * q + 0];
    const float qy = new_xyz[3 * q + 1];
    const float qz = new_xyz[3 * q + 2];
    const float q2 = fmaf(qz, qz, fmaf(qy, qy, qx * qx));
    const float R2 = (float)(0.08 * 0.08);
    const unsigned lmask = (1u << lane) - 1u;

    const int cxq = min(G - 1, max(0, (int)(qx * G)));
    const int cyq = min(G - 1, max(0, (int)(qy * G)));
    const int czq = min(G - 1, max(0, (int)(qz * G)));
    const int xlo = max(cxq - 1, 0), xhi = min(cxq + 1, G - 1);
    const int ylo = max(cyq - 1, 0), yhi = min(cyq + 1, G - 1);
    const int zlo = max(czq - 1, 0), zhi = min(czq + 1, G - 1);

    // enumerate this warp's parity-share of the (z,y) ranges (R3 chain exact)
    int count = 0;
    int r = 0;
    for (int cz = zlo; cz <= zhi; cz++) {
        for (int cy = ylo; cy <= yhi; cy++) {
            if ((r & 1) == sub) {
                int rowbase = (cz * G + cy) * G;
                int rs = g_cell_start[rowbase + xlo];
                int re = g_cell_start[rowbase + xhi + 1];
                for (int base = rs; base < re; base += 32) {
                    int i = base + lane;
                    bool v = i < re;
                    float4 pt = v ? g_sorted_pts[i] : make_float4(0.f, 0.f, 0.f, 1e30f);
                    float cross = fmaf(qz, pt.z, fmaf(qy, pt.y, qx * pt.x));
                    float d2 = fmaf(-2.0f, cross, q2 + pt.w);
                    bool pred = v && (d2 < R2);
                    unsigned m = __ballot_sync(0xffffffffu, pred);
                    if (pred) {
                        int slot = count + __popc(m & lmask);
                        if (slot < MAXBUF) buf[wq][slot] = g_sorted_idx[i];
                    }
                    count += __popc(m);
                }
            }
            r++;
        }
    }
    __syncwarp();

    // per-warp sort: smallest 32 of this warp's candidates -> k[0] ascending
    int nbuf = min(count, MAXBUF);
    int k[4];
#pragma unroll
    for (int j = 0; j < 4; j++) {
        int e = j * 32 + lane;
        k[j] = (e < nbuf) ? buf[wq][e] : 0x7fffffff;
    }
    bitonic128(k, lane);

    pair[s][sub][lane] = k[0];
    if (lane == 0) pcnt[s][sub] = count;
    __syncthreads();

    // bitonic half-cleaner merge: both warps compute identical result
    int A = pair[s][0][lane];
    int B = pair[s][1][31 - lane];
    int c = min(A, B);                   // smallest 32 of union, bitonic
#pragma unroll
    for (int st = 16; st >= 1; st >>= 1) {
        int other = __shfl_xor_sync(0xffffffffu, c, st);
        c = (lane & st) ? max(c, other) : min(c, other);
    }
    const int count_t = pcnt[s][0] + pcnt[s][1];
    const int first = __shfl_sync(0xffffffffu, c, 0);
    const int c32   = min(count_t, SS);
    const int sel   = (lane < c32) ? c : ((count_t > 0) ? first : 0);
    const float idnv = (count_t == 0 || lane < count_t) ? 1.0f : 0.0f;

    // split epilogue (R3-style direct gathers, high MLP)
    const size_t cs = (size_t)PP * SS;
    const size_t ob = (((size_t)b * (C_FEAT + 3)) * PP + p) * SS + lane;
    const float4* __restrict__ ft = (const float4*)g_featT;
    const int fb = sel * (C_FEAT / 4);

    if (sub == 0) {
        float4 ps = g_pts[sel];
        out[ob + 0 * cs] = ps.x - qx;
        out[ob + 1 * cs] = ps.y - qy;
        out[ob + 2 * cs] = ps.z - qz;
        size_t o = ob + 3 * cs;
#pragma unroll
        for (int g = 0; g < 8; g++) {           // feature channels 0..31
            float4 vv = ft[fb + g];
            out[o] = vv.x; o += cs;
            out[o] = vv.y; o += cs;
            out[o] = vv.z; o += cs;
            out[o] = vv.w; o += cs;
        }
    } else {
        size_t o = ob + 35 * cs;                // channels 35..66 = feat 32..63
#pragma unroll
        for (int g = 8; g < 16; g++) {
            float4 vv = ft[fb + g];
            out[o] = vv.x; o += cs;
            out[o] = vv.y; o += cs;
            out[o] = vv.z; o += cs;
            out[o] = vv.w; o += cs;
        }
        if (write_idn)
            out[(size_t)OUT_F + (size_t)q * SS + lane] = idnv;
    }
}

// ---------------------------------------------------------------------------
extern "C" void kernel_launch(void* const* d_in, const int* in_sizes, int n_in,
                              void* d_out, int out_size) {
    const float* xyz      = (const float*)d_in[0];   // (20000, 3)
    const float* new_xyz  = (const float*)d_in[1];   // (2, 2048, 3)
    const float* features = (const float*)d_in[2];   // (64, 20000)
    float* out = (float*)d_out;

    void* cnt_ptr = nullptr;
    cudaGetSymbolAddress(&cnt_ptr, g_cell_count);
    cudaMemsetAsync(cnt_ptr, 0, NCELLS * sizeof(int));

    prep_hist_kernel<<<(N_PTS + 255) / 256, 256>>>(xyz);
    scan_transpose_kernel<<<1 + 625 * 2, 256>>>(features);
    scatter_kernel<<<(N_PTS + 255) / 256, 256>>>();

    int write_idn = (out_size >= OUT_F + NQ * SS) ? 1 : 0;
    query_group_kernel<<<NQ / QW, QW * 64>>>(new_xyz, out, write_idn);
}